// round 13
// baseline (speedup 1.0000x reference)
#include <cuda_runtime.h>
#include <cuda_fp16.h>
#include <cuda_bf16.h>

// ---------------------------------------------------------------------------
// OctreeInterp R12b (identical to R12; R12 bench hit an infra failure).
// R12 = R11 (z-pair fused 128B gathers, T=8) + zero-row sink.
//  * Invalid corners now index a permanent all-zeros row (idx = nnum; BSS
//    zero, never written by prep) => gathers are UNCONDITIONAL: removes
//    FSETP + 4x zero-MOV per gather (~20 inst/thread) while the extra loads
//    all hit one hot 64B line (coalesced, ~free in L1).
//  * Weights exchanged pre-converted as half2 bit patterns (saves 3 cvt).
//  * Kept: fp16 staging (uint4 prep), z-pair LDG.128 gathers, fp16 tree
//    accumulation + xor-shfl half merge, idx+1 table with no clear pass,
//    binsearch fallback for out-of-table keys (off in-bench).
// ---------------------------------------------------------------------------

#define TABLE_MAX (1 << 24)            // supports depth <= 8
__device__ int g_table[TABLE_MAX];     // idx+1 ; 0 = empty

#define MAX_DATA_ELEMS (1 << 24)       // 16M halves = 32 MB scratch
__device__ __half g_data_h[MAX_DATA_ELEMS];

// Fused prep: i < n8 -> convert 2x float4 -> uint4 of 8 halves (16B store);
//             i < nnum -> table scatter. Row `nnum` of g_data_h is never
//             written: it stays BSS-zero (the invalid-corner sink row).
__global__ void __launch_bounds__(256)
prep_k(const float4* __restrict__ src4, int n8,
       const int* __restrict__ keys, int nnum,
       const int* __restrict__ depth_p) {
    int i = blockIdx.x * blockDim.x + threadIdx.x;
    if (i < n8) {
        float4 a = src4[2 * i];
        float4 b = src4[2 * i + 1];
        __half2 h0 = __floats2half2_rn(a.x, a.y);
        __half2 h1 = __floats2half2_rn(a.z, a.w);
        __half2 h2 = __floats2half2_rn(b.x, b.y);
        __half2 h3 = __floats2half2_rn(b.z, b.w);
        uint4 o;
        o.x = *reinterpret_cast<unsigned*>(&h0);
        o.y = *reinterpret_cast<unsigned*>(&h1);
        o.z = *reinterpret_cast<unsigned*>(&h2);
        o.w = *reinterpret_cast<unsigned*>(&h3);
        reinterpret_cast<uint4*>(g_data_h)[i] = o;
    }
    if (i < nnum) {
        int depth = *depth_p;
        long long lim = 1LL << (3 * depth);
        if (lim > (long long)TABLE_MAX) lim = (long long)TABLE_MAX;
        int k = keys[i];
        if (k >= 0 && (long long)k < lim) g_table[k] = i + 1;   // keys unique
    }
}

__device__ __forceinline__ int binsearch(int key, const int* __restrict__ keys,
                                         int nnum) {
    int lo = 0, hi = nnum;
    while (lo < hi) {
        int mid = (lo + hi) >> 1;
        if (keys[mid] < key) lo = mid + 1; else hi = mid;
    }
    return (lo < nnum && keys[lo] == key) ? lo : -1;
}

__device__ __forceinline__ __half2 as_h2(unsigned u) {
    return *reinterpret_cast<__half2*>(&u);
}

// Fast path, C == 32. 256 threads = 32 points x 8 threads.
// Corner numbering: c = (gx<<2)|(gy<<1)|gz ; z-pair j = c>>1.
// Lane duty: own-corner lookup for corner `sub`; gather role (j, h=sub>>2):
// loads halves [8*(sub&3), +8) of row idx(corner 2j+h).
__global__ void __launch_bounds__(256)
interp32z_k(const float4* __restrict__ pts4,
            const int* __restrict__ keys, int nnum,
            const int* __restrict__ depth_p,
            float4* __restrict__ out4, int npts) {
    int sub  = threadIdx.x & 7;
    int p    = blockIdx.x * 32 + (threadIdx.x >> 3);
    bool live = p < npts;
    int pc = min(p, npts - 1);          // tail threads compute on clamped point

    int depth = *depth_p;
    int R = 1 << depth;
    long long R3 = 1LL << (3 * depth);
    int table_lim = (int)(R3 < (long long)TABLE_MAX ? R3 : (long long)TABLE_MAX);
    float scale = (float)(1 << (depth - 1));

    float4 pt = pts4[pc];
    int b = (int)pt.w;

    float xf = (pt.x + 1.0f) * scale - 0.5f;
    float yf = (pt.y + 1.0f) * scale - 0.5f;
    float zf = (pt.z + 1.0f) * scale - 0.5f;
    float fxi = floorf(xf), fyi = floorf(yf), fzi = floorf(zf);
    int xi = (int)fxi, yi = (int)fyi, zi = (int)fzi;
    float frx = xf - fxi, fry = yf - fyi, frz = zf - fzi;

    // --- Own-corner lookup (corner id = sub) ---
    int gx = (sub >> 2) & 1, gy = (sub >> 1) & 1, gz = sub & 1;
    int cx = xi + gx, cy = yi + gy, cz = zi + gz;
    bool inb = ((unsigned)cx < (unsigned)R) &
               ((unsigned)cy < (unsigned)R) &
               ((unsigned)cz < (unsigned)R);
    float w = (gx ? frx : 1.0f - frx) *
              (gy ? fry : 1.0f - fry) *
              (gz ? frz : 1.0f - frz);
    int key = ((b * R + cx) * R + cy) * R + cz;
    int kc  = min(max(key, 0), table_lim - 1);
    int idx = __ldg(&g_table[kc]) - 1;                       // -1 if empty
    if (key >= table_lim) idx = binsearch(key, keys, nnum);  // off in-bench
    bool valid = inb & (key >= 0) & (idx >= 0);
    int   myidx = valid ? idx : nnum;         // invalid -> zero sink row
    float myw   = valid ? w : 0.0f;
    __half2 mywh = __float2half2_rn(myw);     // one cvt per lane
    unsigned mywh_u = *reinterpret_cast<unsigned*>(&mywh);

    // --- Exchange: this lane needs corners (2j + h), j = 0..3 ---
    int h = sub >> 2;                    // 0 or 1 (gz half)
    int     idxs[4];
    __half2 wh[4];
#pragma unroll
    for (int j = 0; j < 4; j++) {
        idxs[j] = __shfl_sync(0xffffffffu, myidx, 2 * j + h, 8);
        wh[j]   = as_h2(__shfl_sync(0xffffffffu, mywh_u, 2 * j + h, 8));
    }

    // wsum in f32: own weight summed across the 8-lane segment (butterfly)
    float s = myw;
    s += __shfl_xor_sync(0xffffffffu, s, 1, 8);
    s += __shfl_xor_sync(0xffffffffu, s, 2, 8);
    s += __shfl_xor_sync(0xffffffffu, s, 4, 8);
    float wsum = s;

    // --- 4 UNCONDITIONAL gathers (16B LDG.128); invalid rows hit the hot
    //     all-zeros sink row. For pair j, lanes 0-3 cover row i0, lanes 4-7
    //     row i1 -> one 128B line when indices adjacent. ---
    int cg = sub & 3;                    // 16B chunk within row
    const uint4* data_h4 = reinterpret_cast<const uint4*>(g_data_h);
    uint4 rows[4];
#pragma unroll
    for (int j = 0; j < 4; j++)
        rows[j] = data_h4[(size_t)((unsigned)idxs[j] * 4u + (unsigned)cg)];

    // --- fp16 accumulation: 4 slots (8 channels) over this half's corners ---
    __half2 acc0 = __hfma2(wh[1], as_h2(rows[1].x), __hmul2(wh[0], as_h2(rows[0].x)));
    __half2 acc1 = __hfma2(wh[1], as_h2(rows[1].y), __hmul2(wh[0], as_h2(rows[0].y)));
    __half2 acc2 = __hfma2(wh[1], as_h2(rows[1].z), __hmul2(wh[0], as_h2(rows[0].z)));
    __half2 acc3 = __hfma2(wh[1], as_h2(rows[1].w), __hmul2(wh[0], as_h2(rows[0].w)));
    __half2 bcc0 = __hfma2(wh[3], as_h2(rows[3].x), __hmul2(wh[2], as_h2(rows[2].x)));
    __half2 bcc1 = __hfma2(wh[3], as_h2(rows[3].y), __hmul2(wh[2], as_h2(rows[2].y)));
    __half2 bcc2 = __hfma2(wh[3], as_h2(rows[3].z), __hmul2(wh[2], as_h2(rows[2].z)));
    __half2 bcc3 = __hfma2(wh[3], as_h2(rows[3].w), __hmul2(wh[2], as_h2(rows[2].w)));
    acc0 = __hadd2(acc0, bcc0);
    acc1 = __hadd2(acc1, bcc1);
    acc2 = __hadd2(acc2, bcc2);
    acc3 = __hadd2(acc3, bcc3);

    // --- Merge gz halves: lanes sub and sub^4 hold same channels ---
    unsigned u0 = *reinterpret_cast<unsigned*>(&acc0);
    unsigned u1 = *reinterpret_cast<unsigned*>(&acc1);
    unsigned u2 = *reinterpret_cast<unsigned*>(&acc2);
    unsigned u3 = *reinterpret_cast<unsigned*>(&acc3);
    acc0 = __hadd2(acc0, as_h2(__shfl_xor_sync(0xffffffffu, u0, 4, 8)));
    acc1 = __hadd2(acc1, as_h2(__shfl_xor_sync(0xffffffffu, u1, 4, 8)));
    acc2 = __hadd2(acc2, as_h2(__shfl_xor_sync(0xffffffffu, u2, 4, 8)));
    acc3 = __hadd2(acc3, as_h2(__shfl_xor_sync(0xffffffffu, u3, 4, 8)));

    // --- Epilogue: lane writes 4 floats. h=0 -> slots 0,1 ; h=1 -> slots 2,3.
    //     out float4 index = p*8 + 2*cg + h ---
    __half2 sa = h ? acc2 : acc0;
    __half2 sb = h ? acc3 : acc1;
    float2 fa = __half22float2(sa);
    float2 fb = __half22float2(sb);
    float inv = 1.0f / (wsum + 1e-12f);
    if (live)
        out4[(size_t)p * 8 + 2 * cg + h] =
            make_float4(fa.x * inv, fa.y * inv, fb.x * inv, fb.y * inv);
}

// Scalar f32 fallback (general C): one thread per (point, channel).
__global__ void interp_scalar_k(const float* __restrict__ data,
                                const float* __restrict__ pts,
                                const int* __restrict__ keys, int nnum,
                                const int* __restrict__ depth_p,
                                float* __restrict__ out,
                                int npts, int C) {
    long long t = (long long)blockIdx.x * blockDim.x + threadIdx.x;
    long long total = (long long)npts * C;
    if (t >= total) return;
    int p = (int)(t / C);
    int c = (int)(t % C);

    int depth = *depth_p;
    int R = 1 << depth;
    long long R3 = 1LL << (3 * depth);
    int table_lim = (int)(R3 < (long long)TABLE_MAX ? R3 : (long long)TABLE_MAX);
    float scale = (float)(1 << (depth - 1));

    const float* pp = pts + (size_t)p * 4;
    float xf = (pp[0] + 1.0f) * scale - 0.5f;
    float yf = (pp[1] + 1.0f) * scale - 0.5f;
    float zf = (pp[2] + 1.0f) * scale - 0.5f;
    int b = (int)pp[3];
    float fxi = floorf(xf), fyi = floorf(yf), fzi = floorf(zf);
    int xi = (int)fxi, yi = (int)fyi, zi = (int)fzi;
    float frx = xf - fxi, fry = yf - fyi, frz = zf - fzi;

    float acc = 0.f, wsum = 0.f;
#pragma unroll
    for (int g = 0; g < 8; g++) {
        int gx = (g >> 2) & 1, gy = (g >> 1) & 1, gz = g & 1;
        int cx = xi + gx, cy = yi + gy, cz = zi + gz;
        bool inb = (cx >= 0) & (cx < R) & (cy >= 0) & (cy < R) & (cz >= 0) & (cz < R);
        if (!inb) continue;
        int key = ((b * R + cx) * R + cy) * R + cz;
        int idx;
        if (key >= 0 && key < table_lim) idx = g_table[key] - 1;
        else idx = binsearch(key, keys, nnum);
        if (idx >= 0) {
            float w = (gx ? frx : 1.0f - frx) *
                      (gy ? fry : 1.0f - fry) *
                      (gz ? frz : 1.0f - frz);
            acc  += w * data[(size_t)idx * C + c];
            wsum += w;
        }
    }
    out[(size_t)p * C + c] = acc / (wsum + 1e-12f);
}

// Table-only build for the fallback path.
__global__ void build_table_k(const int* __restrict__ keys, int nnum,
                              const int* __restrict__ depth_p) {
    int i = blockIdx.x * blockDim.x + threadIdx.x;
    if (i >= nnum) return;
    int depth = *depth_p;
    long long lim = 1LL << (3 * depth);
    if (lim > (long long)TABLE_MAX) lim = (long long)TABLE_MAX;
    int k = keys[i];
    if (k >= 0 && (long long)k < lim) g_table[k] = i + 1;
}

extern "C" void kernel_launch(void* const* d_in, const int* in_sizes, int n_in,
                              void* d_out, int out_size) {
    const float* data      = (const float*)d_in[0];
    const float* pts       = (const float*)d_in[1];
    const int*   node_keys = (const int*)d_in[2];
    const int*   depth_p   = (const int*)d_in[3];
    float*       out       = (float*)d_out;

    int npts = in_sizes[1] / 4;
    int nnum = in_sizes[2];
    int C    = (nnum > 0) ? in_sizes[0] / nnum : 32;

    // need one extra sink row beyond the data: (nnum+1)*C halves
    if (C == 32 && (long long)(nnum + 1) * C <= (long long)MAX_DATA_ELEMS) {
        int n8 = (nnum * C) / 8;                  // uint4-of-8-halves count
        int prep_n = n8 > nnum ? n8 : nnum;
        prep_k<<<(prep_n + 255) / 256, 256>>>((const float4*)data, n8,
                                              node_keys, nnum, depth_p);
        int blocks = (npts + 31) / 32;            // 32 points / 256-thread block
        interp32z_k<<<blocks, 256>>>((const float4*)pts, node_keys, nnum,
                                     depth_p, (float4*)out, npts);
    } else {
        build_table_k<<<(nnum + 255) / 256, 256>>>(node_keys, nnum, depth_p);
        long long total = (long long)npts * C;
        int blocks = (int)((total + 255) / 256);
        interp_scalar_k<<<blocks, 256>>>(data, pts, node_keys, nnum, depth_p,
                                         out, npts, C);
    }
}

// round 15
// speedup vs baseline: 1.0298x; 1.0298x over previous
#include <cuda_runtime.h>
#include <cuda_fp16.h>
#include <cuda_bf16.h>

// ---------------------------------------------------------------------------
// OctreeInterp R14b (identical to R14; R14 bench hit an infra failure).
// R14 = hybrid of measured-best halves:
//  * R11's PREDICATED gathers (L1 is the binder; unconditional sink-row
//    gathers in R12 raised L1 73->78% and regressed). Gate = idxs[j] >= 0.
//  * R12's issue diet: weights exchanged pre-converted as half2 bit patterns
//    (1 cvt/lane), wsum via 3-shfl butterfly.
//  * Kept: T=8 z-pair fused LDG.128 gathers (adjacent node indices from the
//    sorted key array share a 128B line), fp16 staging (uint4 prep), fp16
//    tree accumulation + xor-shfl half merge, idx+1 inverse table with no
//    clear pass (BSS zeros + idempotent scatter), binsearch fallback for
//    out-of-table keys (off in-bench).
// ---------------------------------------------------------------------------

#define TABLE_MAX (1 << 24)            // supports depth <= 8
__device__ int g_table[TABLE_MAX];     // idx+1 ; 0 = empty

#define MAX_DATA_ELEMS (1 << 24)       // 16M halves = 32 MB scratch
__device__ __half g_data_h[MAX_DATA_ELEMS];

// Fused prep: i < n8 -> convert 2x float4 -> uint4 of 8 halves (16B store);
//             i < nnum -> table scatter.
__global__ void __launch_bounds__(256)
prep_k(const float4* __restrict__ src4, int n8,
       const int* __restrict__ keys, int nnum,
       const int* __restrict__ depth_p) {
    int i = blockIdx.x * blockDim.x + threadIdx.x;
    if (i < n8) {
        float4 a = src4[2 * i];
        float4 b = src4[2 * i + 1];
        __half2 h0 = __floats2half2_rn(a.x, a.y);
        __half2 h1 = __floats2half2_rn(a.z, a.w);
        __half2 h2 = __floats2half2_rn(b.x, b.y);
        __half2 h3 = __floats2half2_rn(b.z, b.w);
        uint4 o;
        o.x = *reinterpret_cast<unsigned*>(&h0);
        o.y = *reinterpret_cast<unsigned*>(&h1);
        o.z = *reinterpret_cast<unsigned*>(&h2);
        o.w = *reinterpret_cast<unsigned*>(&h3);
        reinterpret_cast<uint4*>(g_data_h)[i] = o;
    }
    if (i < nnum) {
        int depth = *depth_p;
        long long lim = 1LL << (3 * depth);
        if (lim > (long long)TABLE_MAX) lim = (long long)TABLE_MAX;
        int k = keys[i];
        if (k >= 0 && (long long)k < lim) g_table[k] = i + 1;   // keys unique
    }
}

__device__ __forceinline__ int binsearch(int key, const int* __restrict__ keys,
                                         int nnum) {
    int lo = 0, hi = nnum;
    while (lo < hi) {
        int mid = (lo + hi) >> 1;
        if (keys[mid] < key) lo = mid + 1; else hi = mid;
    }
    return (lo < nnum && keys[lo] == key) ? lo : -1;
}

__device__ __forceinline__ __half2 as_h2(unsigned u) {
    return *reinterpret_cast<__half2*>(&u);
}

// Fast path, C == 32. 256 threads = 32 points x 8 threads.
// Corner numbering: c = (gx<<2)|(gy<<1)|gz ; z-pair j = c>>1.
// Lane duty: own-corner lookup for corner `sub`; gather role (j, h=sub>>2):
// loads halves [8*(sub&3), +8) of row idx(corner 2j+h).
__global__ void __launch_bounds__(256)
interp32z_k(const float4* __restrict__ pts4,
            const int* __restrict__ keys, int nnum,
            const int* __restrict__ depth_p,
            float4* __restrict__ out4, int npts) {
    int sub  = threadIdx.x & 7;
    int p    = blockIdx.x * 32 + (threadIdx.x >> 3);
    bool live = p < npts;
    int pc = min(p, npts - 1);          // tail threads compute on clamped point

    int depth = *depth_p;
    int R = 1 << depth;
    long long R3 = 1LL << (3 * depth);
    int table_lim = (int)(R3 < (long long)TABLE_MAX ? R3 : (long long)TABLE_MAX);
    float scale = (float)(1 << (depth - 1));

    float4 pt = pts4[pc];
    int b = (int)pt.w;

    float xf = (pt.x + 1.0f) * scale - 0.5f;
    float yf = (pt.y + 1.0f) * scale - 0.5f;
    float zf = (pt.z + 1.0f) * scale - 0.5f;
    float fxi = floorf(xf), fyi = floorf(yf), fzi = floorf(zf);
    int xi = (int)fxi, yi = (int)fyi, zi = (int)fzi;
    float frx = xf - fxi, fry = yf - fyi, frz = zf - fzi;

    // --- Own-corner lookup (corner id = sub) ---
    int gx = (sub >> 2) & 1, gy = (sub >> 1) & 1, gz = sub & 1;
    int cx = xi + gx, cy = yi + gy, cz = zi + gz;
    bool inb = ((unsigned)cx < (unsigned)R) &
               ((unsigned)cy < (unsigned)R) &
               ((unsigned)cz < (unsigned)R);
    float w = (gx ? frx : 1.0f - frx) *
              (gy ? fry : 1.0f - fry) *
              (gz ? frz : 1.0f - frz);
    int key = ((b * R + cx) * R + cy) * R + cz;
    int kc  = min(max(key, 0), table_lim - 1);
    int idx = __ldg(&g_table[kc]) - 1;                       // -1 if empty
    if (key >= table_lim) idx = binsearch(key, keys, nnum);  // off in-bench
    bool valid = inb & (key >= 0) & (idx >= 0);
    int   myidx = valid ? idx : -1;           // -1 sentinel gates the gather
    float myw   = valid ? w : 0.0f;
    __half2 mywh = __float2half2_rn(myw);     // one cvt per lane
    unsigned mywh_u = *reinterpret_cast<unsigned*>(&mywh);

    // --- Exchange: this lane needs corners (2j + h), j = 0..3 ---
    int h = sub >> 2;                    // 0 or 1 (gz half)
    int     idxs[4];
    __half2 wh[4];
#pragma unroll
    for (int j = 0; j < 4; j++) {
        idxs[j] = __shfl_sync(0xffffffffu, myidx, 2 * j + h, 8);
        wh[j]   = as_h2(__shfl_sync(0xffffffffu, mywh_u, 2 * j + h, 8));
    }

    // wsum in f32: own weight summed across the 8-lane segment (butterfly)
    float s = myw;
    s += __shfl_xor_sync(0xffffffffu, s, 1, 8);
    s += __shfl_xor_sync(0xffffffffu, s, 2, 8);
    s += __shfl_xor_sync(0xffffffffu, s, 4, 8);
    float wsum = s;

    // --- 4 PREDICATED gathers (16B LDG.128). For pair j, lanes 0-3 cover
    //     row i0, lanes 4-7 row i1 -> one 128B line when indices adjacent.
    //     ~24% invalid corners skip their load (L1 is the binder). ---
    int cg = sub & 3;                    // 16B chunk within row
    const uint4* data_h4 = reinterpret_cast<const uint4*>(g_data_h);
    uint4 rows[4];
#pragma unroll
    for (int j = 0; j < 4; j++) {
        uint4 r = make_uint4(0u, 0u, 0u, 0u);
        if (idxs[j] >= 0)                          // @P-predicated 16B load
            r = data_h4[(size_t)((unsigned)idxs[j] * 4u + (unsigned)cg)];
        rows[j] = r;
    }

    // --- fp16 accumulation: 4 slots (8 channels) over this half's corners ---
    __half2 acc0 = __hfma2(wh[1], as_h2(rows[1].x), __hmul2(wh[0], as_h2(rows[0].x)));
    __half2 acc1 = __hfma2(wh[1], as_h2(rows[1].y), __hmul2(wh[0], as_h2(rows[0].y)));
    __half2 acc2 = __hfma2(wh[1], as_h2(rows[1].z), __hmul2(wh[0], as_h2(rows[0].z)));
    __half2 acc3 = __hfma2(wh[1], as_h2(rows[1].w), __hmul2(wh[0], as_h2(rows[0].w)));
    __half2 bcc0 = __hfma2(wh[3], as_h2(rows[3].x), __hmul2(wh[2], as_h2(rows[2].x)));
    __half2 bcc1 = __hfma2(wh[3], as_h2(rows[3].y), __hmul2(wh[2], as_h2(rows[2].y)));
    __half2 bcc2 = __hfma2(wh[3], as_h2(rows[3].z), __hmul2(wh[2], as_h2(rows[2].z)));
    __half2 bcc3 = __hfma2(wh[3], as_h2(rows[3].w), __hmul2(wh[2], as_h2(rows[2].w)));
    acc0 = __hadd2(acc0, bcc0);
    acc1 = __hadd2(acc1, bcc1);
    acc2 = __hadd2(acc2, bcc2);
    acc3 = __hadd2(acc3, bcc3);

    // --- Merge gz halves: lanes sub and sub^4 hold same channels ---
    unsigned u0 = *reinterpret_cast<unsigned*>(&acc0);
    unsigned u1 = *reinterpret_cast<unsigned*>(&acc1);
    unsigned u2 = *reinterpret_cast<unsigned*>(&acc2);
    unsigned u3 = *reinterpret_cast<unsigned*>(&acc3);
    acc0 = __hadd2(acc0, as_h2(__shfl_xor_sync(0xffffffffu, u0, 4, 8)));
    acc1 = __hadd2(acc1, as_h2(__shfl_xor_sync(0xffffffffu, u1, 4, 8)));
    acc2 = __hadd2(acc2, as_h2(__shfl_xor_sync(0xffffffffu, u2, 4, 8)));
    acc3 = __hadd2(acc3, as_h2(__shfl_xor_sync(0xffffffffu, u3, 4, 8)));

    // --- Epilogue: lane writes 4 floats. h=0 -> slots 0,1 ; h=1 -> slots 2,3.
    //     out float4 index = p*8 + 2*cg + h ---
    __half2 sa = h ? acc2 : acc0;
    __half2 sb = h ? acc3 : acc1;
    float2 fa = __half22float2(sa);
    float2 fb = __half22float2(sb);
    float inv = 1.0f / (wsum + 1e-12f);
    if (live)
        out4[(size_t)p * 8 + 2 * cg + h] =
            make_float4(fa.x * inv, fa.y * inv, fb.x * inv, fb.y * inv);
}

// Scalar f32 fallback (general C): one thread per (point, channel).
__global__ void interp_scalar_k(const float* __restrict__ data,
                                const float* __restrict__ pts,
                                const int* __restrict__ keys, int nnum,
                                const int* __restrict__ depth_p,
                                float* __restrict__ out,
                                int npts, int C) {
    long long t = (long long)blockIdx.x * blockDim.x + threadIdx.x;
    long long total = (long long)npts * C;
    if (t >= total) return;
    int p = (int)(t / C);
    int c = (int)(t % C);

    int depth = *depth_p;
    int R = 1 << depth;
    long long R3 = 1LL << (3 * depth);
    int table_lim = (int)(R3 < (long long)TABLE_MAX ? R3 : (long long)TABLE_MAX);
    float scale = (float)(1 << (depth - 1));

    const float* pp = pts + (size_t)p * 4;
    float xf = (pp[0] + 1.0f) * scale - 0.5f;
    float yf = (pp[1] + 1.0f) * scale - 0.5f;
    float zf = (pp[2] + 1.0f) * scale - 0.5f;
    int b = (int)pp[3];
    float fxi = floorf(xf), fyi = floorf(yf), fzi = floorf(zf);
    int xi = (int)fxi, yi = (int)fyi, zi = (int)fzi;
    float frx = xf - fxi, fry = yf - fyi, frz = zf - fzi;

    float acc = 0.f, wsum = 0.f;
#pragma unroll
    for (int g = 0; g < 8; g++) {
        int gx = (g >> 2) & 1, gy = (g >> 1) & 1, gz = g & 1;
        int cx = xi + gx, cy = yi + gy, cz = zi + gz;
        bool inb = (cx >= 0) & (cx < R) & (cy >= 0) & (cy < R) & (cz >= 0) & (cz < R);
        if (!inb) continue;
        int key = ((b * R + cx) * R + cy) * R + cz;
        int idx;
        if (key >= 0 && key < table_lim) idx = g_table[key] - 1;
        else idx = binsearch(key, keys, nnum);
        if (idx >= 0) {
            float w = (gx ? frx : 1.0f - frx) *
                      (gy ? fry : 1.0f - fry) *
                      (gz ? frz : 1.0f - frz);
            acc  += w * data[(size_t)idx * C + c];
            wsum += w;
        }
    }
    out[(size_t)p * C + c] = acc / (wsum + 1e-12f);
}

// Table-only build for the fallback path.
__global__ void build_table_k(const int* __restrict__ keys, int nnum,
                              const int* __restrict__ depth_p) {
    int i = blockIdx.x * blockDim.x + threadIdx.x;
    if (i >= nnum) return;
    int depth = *depth_p;
    long long lim = 1LL << (3 * depth);
    if (lim > (long long)TABLE_MAX) lim = (long long)TABLE_MAX;
    int k = keys[i];
    if (k >= 0 && (long long)k < lim) g_table[k] = i + 1;
}

extern "C" void kernel_launch(void* const* d_in, const int* in_sizes, int n_in,
                              void* d_out, int out_size) {
    const float* data      = (const float*)d_in[0];
    const float* pts       = (const float*)d_in[1];
    const int*   node_keys = (const int*)d_in[2];
    const int*   depth_p   = (const int*)d_in[3];
    float*       out       = (float*)d_out;

    int npts = in_sizes[1] / 4;
    int nnum = in_sizes[2];
    int C    = (nnum > 0) ? in_sizes[0] / nnum : 32;

    if (C == 32 && (long long)nnum * C <= (long long)MAX_DATA_ELEMS) {
        int n8 = (nnum * C) / 8;                  // uint4-of-8-halves count
        int prep_n = n8 > nnum ? n8 : nnum;
        prep_k<<<(prep_n + 255) / 256, 256>>>((const float4*)data, n8,
                                              node_keys, nnum, depth_p);
        int blocks = (npts + 31) / 32;            // 32 points / 256-thread block
        interp32z_k<<<blocks, 256>>>((const float4*)pts, node_keys, nnum,
                                     depth_p, (float4*)out, npts);
    } else {
        build_table_k<<<(nnum + 255) / 256, 256>>>(node_keys, nnum, depth_p);
        long long total = (long long)npts * C;
        int blocks = (int)((total + 255) / 256);
        interp_scalar_k<<<blocks, 256>>>(data, pts, node_keys, nnum, depth_p,
                                         out, npts, C);
    }
}